// round 1
// baseline (speedup 1.0000x reference)
#include <cuda_runtime.h>

// GCNFast: out[b,s,t,:] = relu( sum_j relu(AA[i%64,j%64]*GCW[i,j]) * x[b,j,:] + GCB[i,:] )
// with i = t*64+s, j = t'*64+c, x[b,j,:] = h[b,c,t',:].
// Folded into ONE GEMM: C[4096, 16*128] = A[4096,4096] * X[4096, 16*128],
// N-block (128 wide) == one batch b. tf32 mma.sync + cp.async double buffering.

namespace {
constexpr int BM = 128, BN = 128, BK = 32;
constexpr int SA_STRIDE = 36;    // 32 + 4 pad  (stride % 32 == 4 -> conflict-free A frags)
constexpr int SX_STRIDE = 136;   // 128 + 8 pad (stride % 32 == 8 -> conflict-free B frags)
constexpr int SA_TILE = BM * SA_STRIDE;   // floats per stage
constexpr int SX_TILE = BK * SX_STRIDE;   // floats per stage
constexpr int SMEM_FLOATS = 2 * SA_TILE + 2 * SX_TILE;
constexpr int SMEM_BYTES = SMEM_FLOATS * 4 + 64 * 8;  // + 64 uint64 AA bitmasks
constexpr int KDIM = 4096;
constexpr int NT = KDIM / BK;  // 128 k-tiles
}

__device__ __forceinline__ unsigned cvt_tf32(float x) {
    unsigned r;
    asm("cvt.rna.tf32.f32 %0, %1;" : "=r"(r) : "f"(x));
    return r;
}

__device__ __forceinline__ void mma8(float (&c)[4],
                                     unsigned a0, unsigned a1, unsigned a2, unsigned a3,
                                     unsigned b0, unsigned b1) {
    asm volatile(
        "mma.sync.aligned.m16n8k8.row.col.f32.tf32.tf32.f32 "
        "{%0,%1,%2,%3}, {%4,%5,%6,%7}, {%8,%9}, {%0,%1,%2,%3};"
        : "+f"(c[0]), "+f"(c[1]), "+f"(c[2]), "+f"(c[3])
        : "r"(a0), "r"(a1), "r"(a2), "r"(a3), "r"(b0), "r"(b1));
}

__device__ __forceinline__ void cp16(float* dst, const float* src) {
    unsigned s = (unsigned)__cvta_generic_to_shared(dst);
    asm volatile("cp.async.cg.shared.global [%0], [%1], 16;" :: "r"(s), "l"(src));
}

__global__ void __launch_bounds__(256)
gcn_tf32_kernel(const float* __restrict__ h, const float* __restrict__ AAm,
                const float* __restrict__ GCW, const float* __restrict__ GCB,
                float* __restrict__ out)
{
    extern __shared__ float smem[];
    float* sA = smem;                       // [2][BM][SA_STRIDE], raw GCW tiles
    float* sX = smem + 2 * SA_TILE;         // [2][BK][SX_STRIDE], gathered h tiles
    unsigned long long* sAA = (unsigned long long*)(smem + SMEM_FLOATS);

    const int tid = threadIdx.x;
    const int bN  = blockIdx.x;   // batch index b (N-block, 128 == d_h)
    const int bM  = blockIdx.y;   // M-block

    // Build AA row bitmasks from the top-left 64x64 of AA_mask (== AA).
    if (tid < 64) {
        const float* row = AAm + (size_t)tid * 4096;
        unsigned long long bits = 0ull;
        #pragma unroll 8
        for (int j = 0; j < 64; ++j)
            bits |= (row[j] != 0.0f) ? (1ull << j) : 0ull;
        sAA[tid] = bits;
    }

    auto load_tiles = [&](int kt, int st) {
        const int k0 = kt * BK;
        // A tile: raw GCW[bM*128 + m, k0 .. k0+31]
        #pragma unroll
        for (int p = 0; p < 4; ++p) {
            int id = tid + p * 256;
            int m = id >> 3, ch = (id & 7) << 2;
            cp16(sA + st * SA_TILE + m * SA_STRIDE + ch,
                 GCW + (size_t)(bM * BM + m) * KDIM + k0 + ch);
        }
        // X tile: row j = k0+kk -> h[bN, c=j&63, t=j>>6, :]
        #pragma unroll
        for (int p = 0; p < 4; ++p) {
            int id = tid + p * 256;
            int kk = id >> 5, ch = (id & 31) << 2;
            int j = k0 + kk;
            int t = j >> 6, c = j & 63;
            cp16(sX + st * SX_TILE + kk * SX_STRIDE + ch,
                 h + (((size_t)(bN * 64 + c) * 64 + t) << 7) + ch);
        }
        asm volatile("cp.async.commit_group;");
    };

    load_tiles(0, 0);
    __syncthreads();   // sAA visible

    const int lane = tid & 31, wid = tid >> 5;
    const int warpM = wid >> 2;   // 0..1 : warp tile 64(M) x 32(N)
    const int warpN = wid & 3;    // 0..3
    const int g = lane >> 2, q = lane & 3;

    // Per-thread A-row bitmasks: row%64 is fixed for the whole K loop.
    unsigned long long mlo[4], mhi[4];
    #pragma unroll
    for (int mt = 0; mt < 4; ++mt) {
        mlo[mt] = sAA[mt * 16 + g];
        mhi[mt] = sAA[mt * 16 + g + 8];
    }

    float acc[4][4][4];
    #pragma unroll
    for (int a = 0; a < 4; ++a)
        #pragma unroll
        for (int b = 0; b < 4; ++b)
            #pragma unroll
            for (int v = 0; v < 4; ++v) acc[a][b][v] = 0.f;

    for (int kt = 0; kt < NT; ++kt) {
        if (kt + 1 < NT) {
            load_tiles(kt + 1, (kt + 1) & 1);
            asm volatile("cp.async.wait_group 1;");
        } else {
            asm volatile("cp.async.wait_group 0;");
        }
        __syncthreads();

        const float* tA = sA + (kt & 1) * SA_TILE;
        const float* tX = sX + (kt & 1) * SX_TILE;
        const int bitbase = (kt & 1) << 5;   // (kt*32) % 64

        #pragma unroll
        for (int kk = 0; kk < 4; ++kk) {
            // B fragments: B[k,n] = X[kk*8+q(+4)][warpN*32 + nt*8 + g]
            unsigned bf[4][2];
            #pragma unroll
            for (int nt = 0; nt < 4; ++nt) {
                int n = warpN * 32 + nt * 8 + g;
                bf[nt][0] = cvt_tf32(tX[(kk * 8 + q    ) * SX_STRIDE + n]);
                bf[nt][1] = cvt_tf32(tX[(kk * 8 + q + 4) * SX_STRIDE + n]);
            }
            #pragma unroll
            for (int mt = 0; mt < 4; ++mt) {
                int r0  = warpM * 64 + mt * 16 + g;
                int col = kk * 8 + q;
                float w0 = tA[ r0      * SA_STRIDE + col    ];
                float w1 = tA[(r0 + 8) * SA_STRIDE + col    ];
                float w2 = tA[ r0      * SA_STRIDE + col + 4];
                float w3 = tA[(r0 + 8) * SA_STRIDE + col + 4];
                int j0 = bitbase + col;
                // A = relu(mask * GCW): keep w only if mask bit set AND w > 0
                unsigned a0 = cvt_tf32(((mlo[mt] >> j0) & 1ull)       ? fmaxf(w0, 0.f) : 0.f);
                unsigned a1 = cvt_tf32(((mhi[mt] >> j0) & 1ull)       ? fmaxf(w1, 0.f) : 0.f);
                unsigned a2 = cvt_tf32(((mlo[mt] >> (j0 + 4)) & 1ull) ? fmaxf(w2, 0.f) : 0.f);
                unsigned a3 = cvt_tf32(((mhi[mt] >> (j0 + 4)) & 1ull) ? fmaxf(w3, 0.f) : 0.f);
                #pragma unroll
                for (int nt = 0; nt < 4; ++nt)
                    mma8(acc[mt][nt], a0, a1, a2, a3, bf[nt][0], bf[nt][1]);
            }
        }
        __syncthreads();
    }

    // Epilogue: relu(acc + GCB[i,:]) scattered to out[b, s=i%64, t=i/64, d]
    #pragma unroll
    for (int mt = 0; mt < 4; ++mt) {
        const int i0 = bM * BM + warpM * 64 + mt * 16 + g;
        #pragma unroll
        for (int r = 0; r < 2; ++r) {
            const int ii = i0 + r * 8;
            const int t = ii >> 6, s = ii & 63;
            float* orow = out + (((size_t)(bN * 64 + s) * 64 + t) << 7);
            const float* brow = GCB + (size_t)ii * 128;
            #pragma unroll
            for (int nt = 0; nt < 4; ++nt) {
                const int d0 = warpN * 32 + nt * 8 + q * 2;
                float2 bias = *(const float2*)(brow + d0);
                float2 v;
                v.x = fmaxf(acc[mt][nt][r * 2 + 0] + bias.x, 0.f);
                v.y = fmaxf(acc[mt][nt][r * 2 + 1] + bias.y, 0.f);
                *(float2*)(orow + d0) = v;
            }
        }
    }
}

extern "C" void kernel_launch(void* const* d_in, const int* in_sizes, int n_in,
                              void* d_out, int out_size) {
    // metadata order: h, e, AA_mask, GCW, GCB
    const float* h   = (const float*)d_in[0];
    const float* AAm = (const float*)d_in[2];
    const float* GCW = (const float*)d_in[3];
    const float* GCB = (const float*)d_in[4];
    float* out = (float*)d_out;

    cudaFuncSetAttribute(gcn_tf32_kernel,
                         cudaFuncAttributeMaxDynamicSharedMemorySize, SMEM_BYTES);
    dim3 grid(16, 32);   // x: batch (N blocks), y: M blocks
    gcn_tf32_kernel<<<grid, 256, SMEM_BYTES>>>(h, AAm, GCW, GCB, out);
}

// round 2
// speedup vs baseline: 1.5477x; 1.5477x over previous
#include <cuda_runtime.h>

// GCNFast folded to ONE GEMM: C[4096, 2048] = A[4096,4096] * X[4096,2048]
//   A = relu(AA_mask .* GCW)  (precomputed -> tf32 bits, 64MB device buffer)
//   X[j, b*128+d] = h[b, j%64, j/64, d] (precomputed -> tf32 bits, 32MB)
//   out[b, i%64, i/64, d] = relu(C[i, b*128+d] + GCB[i,d])
// Main kernel: pure tf32 mma.sync GEMM, cp.async double-buffered.

namespace {
constexpr int BM = 128, BN = 128, BK = 32;
constexpr int SA_STRIDE = 36;    // 32 + 4 pad
constexpr int SX_STRIDE = 136;   // 128 + 8 pad
constexpr int SA_TILE = BM * SA_STRIDE;
constexpr int SX_TILE = BK * SX_STRIDE;
constexpr int SMEM_BYTES = (2 * SA_TILE + 2 * SX_TILE) * 4;
constexpr int KDIM = 4096;
constexpr int NDIM = 2048;
constexpr int NT = KDIM / BK;
}

__device__ unsigned g_A[(size_t)4096 * 4096];   // tf32 bits of relu(mask*GCW)
__device__ unsigned g_X[(size_t)4096 * 2048];   // tf32 bits of gathered h

__device__ __forceinline__ unsigned cvt_tf32(float x) {
    unsigned r;
    asm("cvt.rna.tf32.f32 %0, %1;" : "=r"(r) : "f"(x));
    return r;
}

__device__ __forceinline__ void mma8(float (&c)[4],
                                     unsigned a0, unsigned a1, unsigned a2, unsigned a3,
                                     unsigned b0, unsigned b1) {
    asm volatile(
        "mma.sync.aligned.m16n8k8.row.col.f32.tf32.tf32.f32 "
        "{%0,%1,%2,%3}, {%4,%5,%6,%7}, {%8,%9}, {%0,%1,%2,%3};"
        : "+f"(c[0]), "+f"(c[1]), "+f"(c[2]), "+f"(c[3])
        : "r"(a0), "r"(a1), "r"(a2), "r"(a3), "r"(b0), "r"(b1));
}

__device__ __forceinline__ void cp16(unsigned* dst, const unsigned* src) {
    unsigned s = (unsigned)__cvta_generic_to_shared(dst);
    asm volatile("cp.async.cg.shared.global [%0], [%1], 16;" :: "r"(s), "l"(src));
}

// ---- prep: A = tf32(relu(mask * GCW)); mask read from 64x64 corner of AA_mask ----
__global__ void __launch_bounds__(256)
prep_A_kernel(const float4* __restrict__ AAm4, const float4* __restrict__ GCW4) {
    size_t idx = (size_t)blockIdx.x * blockDim.x + threadIdx.x; // over 4096*1024 float4s
    int i  = (int)(idx >> 10);
    int j4 = (int)(idx & 1023);
    // mask columns (4*j4 .. 4*j4+3) mod 64 are contiguous; AAm row pitch = 4096 floats
    float4 m = AAm4[(size_t)(i & 63) * 1024 + (j4 & 15)];
    float4 w = GCW4[idx];
    uint4 o;
    o.x = cvt_tf32(m.x != 0.f ? fmaxf(w.x, 0.f) : 0.f);
    o.y = cvt_tf32(m.y != 0.f ? fmaxf(w.y, 0.f) : 0.f);
    o.z = cvt_tf32(m.z != 0.f ? fmaxf(w.z, 0.f) : 0.f);
    o.w = cvt_tf32(m.w != 0.f ? fmaxf(w.w, 0.f) : 0.f);
    ((uint4*)g_A)[idx] = o;
}

// ---- prep: X[j, b*128+d] = tf32(h[b, j%64, j/64, d]) ----
__global__ void __launch_bounds__(256)
prep_X_kernel(const float4* __restrict__ h4) {
    size_t idx = (size_t)blockIdx.x * blockDim.x + threadIdx.x; // over 4096*512 float4s
    int j  = (int)(idx >> 9);
    int n4 = (int)(idx & 511);
    int b = n4 >> 5, d4 = n4 & 31;
    int t = j >> 6, c = j & 63;
    float4 v = h4[(size_t)(((b * 64 + c) * 64 + t)) * 32 + d4];
    uint4 o;
    o.x = cvt_tf32(v.x); o.y = cvt_tf32(v.y);
    o.z = cvt_tf32(v.z); o.w = cvt_tf32(v.w);
    ((uint4*)g_X)[idx] = o;
}

// ---- main: pure tf32 GEMM + fused bias/relu/scatter epilogue ----
__global__ void __launch_bounds__(256, 2)
gcn_gemm_kernel(const float* __restrict__ GCB, float* __restrict__ out)
{
    extern __shared__ unsigned smem[];
    unsigned* sA = smem;                 // [2][BM][SA_STRIDE]
    unsigned* sX = smem + 2 * SA_TILE;   // [2][BK][SX_STRIDE]

    const int tid = threadIdx.x;
    const int bN  = blockIdx.x;   // batch b
    const int bM  = blockIdx.y;

    auto load_tiles = [&](int kt, int st) {
        const int k0 = kt * BK;
        #pragma unroll
        for (int p = 0; p < 4; ++p) {
            int id = tid + p * 256;
            int m = id >> 3, ch = (id & 7) << 2;
            cp16(sA + st * SA_TILE + m * SA_STRIDE + ch,
                 g_A + (size_t)(bM * BM + m) * KDIM + k0 + ch);
        }
        #pragma unroll
        for (int p = 0; p < 4; ++p) {
            int id = tid + p * 256;
            int kk = id >> 5, ch = (id & 31) << 2;
            cp16(sX + st * SX_TILE + kk * SX_STRIDE + ch,
                 g_X + (size_t)(k0 + kk) * NDIM + bN * BN + ch);
        }
        asm volatile("cp.async.commit_group;");
    };

    load_tiles(0, 0);

    const int lane = tid & 31, wid = tid >> 5;
    const int warpM = wid >> 2;
    const int warpN = wid & 3;
    const int g = lane >> 2, q = lane & 3;

    float acc[4][4][4];
    #pragma unroll
    for (int a = 0; a < 4; ++a)
        #pragma unroll
        for (int b = 0; b < 4; ++b)
            #pragma unroll
            for (int v = 0; v < 4; ++v) acc[a][b][v] = 0.f;

    for (int kt = 0; kt < NT; ++kt) {
        if (kt + 1 < NT) {
            load_tiles(kt + 1, (kt + 1) & 1);
            asm volatile("cp.async.wait_group 1;");
        } else {
            asm volatile("cp.async.wait_group 0;");
        }
        __syncthreads();

        const unsigned* tA = sA + (kt & 1) * SA_TILE;
        const unsigned* tX = sX + (kt & 1) * SX_TILE;

        #pragma unroll
        for (int kk = 0; kk < 4; ++kk) {
            unsigned bf[4][2];
            #pragma unroll
            for (int nt = 0; nt < 4; ++nt) {
                int n = warpN * 32 + nt * 8 + g;
                bf[nt][0] = tX[(kk * 8 + q    ) * SX_STRIDE + n];
                bf[nt][1] = tX[(kk * 8 + q + 4) * SX_STRIDE + n];
            }
            #pragma unroll
            for (int mt = 0; mt < 4; ++mt) {
                int r0  = warpM * 64 + mt * 16 + g;
                int col = kk * 8 + q;
                unsigned a0 = tA[ r0      * SA_STRIDE + col    ];
                unsigned a1 = tA[(r0 + 8) * SA_STRIDE + col    ];
                unsigned a2 = tA[ r0      * SA_STRIDE + col + 4];
                unsigned a3 = tA[(r0 + 8) * SA_STRIDE + col + 4];
                #pragma unroll
                for (int nt = 0; nt < 4; ++nt)
                    mma8(acc[mt][nt], a0, a1, a2, a3, bf[nt][0], bf[nt][1]);
            }
        }
        __syncthreads();
    }

    // Epilogue: relu(acc + GCB[i,:]) -> out[b, s=i%64, t=i/64, d]
    #pragma unroll
    for (int mt = 0; mt < 4; ++mt) {
        const int i0 = bM * BM + warpM * 64 + mt * 16 + g;
        #pragma unroll
        for (int r = 0; r < 2; ++r) {
            const int ii = i0 + r * 8;
            const int t = ii >> 6, s = ii & 63;
            float* orow = out + (((size_t)(bN * 64 + s) * 64 + t) << 7);
            const float* brow = GCB + (size_t)ii * 128;
            #pragma unroll
            for (int nt = 0; nt < 4; ++nt) {
                const int d0 = warpN * 32 + nt * 8 + q * 2;
                float2 bias = *(const float2*)(brow + d0);
                float2 v;
                v.x = fmaxf(acc[mt][nt][r * 2 + 0] + bias.x, 0.f);
                v.y = fmaxf(acc[mt][nt][r * 2 + 1] + bias.y, 0.f);
                *(float2*)(orow + d0) = v;
            }
        }
    }
}

extern "C" void kernel_launch(void* const* d_in, const int* in_sizes, int n_in,
                              void* d_out, int out_size) {
    // metadata order: h, e, AA_mask, GCW, GCB
    const float* h   = (const float*)d_in[0];
    const float* AAm = (const float*)d_in[2];
    const float* GCW = (const float*)d_in[3];
    const float* GCB = (const float*)d_in[4];
    float* out = (float*)d_out;

    prep_A_kernel<<<(4096 * 1024) / 256, 256>>>((const float4*)AAm, (const float4*)GCW);
    prep_X_kernel<<<(4096 * 512) / 256, 256>>>((const float4*)h);

    cudaFuncSetAttribute(gcn_gemm_kernel,
                         cudaFuncAttributeMaxDynamicSharedMemorySize, SMEM_BYTES);
    dim3 grid(16, 32);
    gcn_gemm_kernel<<<grid, 256, SMEM_BYTES>>>(GCB, out);
}